// round 8
// baseline (speedup 1.0000x reference)
#include <cuda_runtime.h>
#include <cuda_bf16.h>
#include <cstdint>

// y_t = d*y_{t-1} + x_t   per channel, y_{-1} = 0.
// x: [BSZ=8, SEQ=4096, CH=1024] fp32, d: [CH] fp32.
//
// Chained segment handoff. Each (batch, 32-channel group) column is split
// into SEGS=8 segments of 512 steps -> 2048 blocks (seg-major bid order, so
// every predecessor launches >= 1 wave earlier). Per block: 4 chunks of 128
// steps, 256 thr = 8 subtiles x 32 ch, one bar.sync per chunk, every warp
// redundantly combines the 8 subtile aggregates (multiplier d^16) and keeps
// a replicated carry.
// seg>0 blocks seed carry from the predecessor's published per-channel
// carries. ONLY WARP 0 spins on the flag (volatile loads bypass L1; 8 warps
// x ~1800 blocks hammering one L2 line would rob the predecessors of LTS
// bandwidth); it parks the 32 carries in smem and a single barrier
// broadcasts them. Publish happens right after the final chunk's combine,
// before that chunk's store loop.

#define BSZ    8
#define SEQ    4096
#define CH     1024
#define TSUB   16
#define NSUB   8
#define NTHR   (NSUB * 32)          // 256
#define CHUNK  (TSUB * NSUB)        // 128
#define SEGS   8
#define SEG_LEN (SEQ / SEGS)        // 512
#define NCHSEG (SEG_LEN / CHUNK)    // 4 chunks per segment
#define CGRPS  (CH / 32)            // 32
#define NGRP   (BSZ * CGRPS)        // 256 column groups

__device__ float    g_carry[SEGS * NGRP * 32];
__device__ unsigned g_flag[SEGS * NGRP];

__global__ void init_flags_kernel()
{
    int i = blockIdx.x * blockDim.x + threadIdx.x;
    if (i < SEGS * NGRP) g_flag[i] = 0u;
}

__global__ __launch_bounds__(NTHR, 2)
void cummulsum_kernel(const float* __restrict__ x,
                      const float* __restrict__ d,
                      float* __restrict__ y)
{
    __shared__ float subAgg[2][NSUB][32];   // double-buffered by chunk parity
    __shared__ float carrySh[32];

    const int tid  = threadIdx.x;
    const int lane = tid & 31;
    const int s    = tid >> 5;              // subtile index 0..7
    const int bid  = blockIdx.x;
    const int seg  = bid >> 8;              // bid / NGRP  (seg-major order)
    const int grp  = bid & (NGRP - 1);      // column group 0..255
    const int b    = grp >> 5;              // batch
    const int cg   = grp & 31;              // channel group
    const int c    = cg * 32 + lane;        // channel

    const float dc = __ldg(d + c);
    // dT = dc^TSUB = dc^16
    float dT = dc * dc;  dT = dT * dT;  dT = dT * dT;  dT = dT * dT;

    const size_t colBase = ((size_t)b * SEQ) * CH + (size_t)c;
    const size_t segOff  = (size_t)(seg * SEG_LEN + s * TSUB) * CH;
    const float* xp = x + colBase + segOff;
    float*       yp = y + colBase + segOff;

    float xa[TSUB];
    float xb[TSUB];

    // Prologue loads FIRST so DRAM latency overlaps the handoff spin.
    #pragma unroll
    for (int i = 0; i < TSUB; i++) xa[i] = xp[(size_t)i * CH];

    // Seed carry from predecessor segment; only warp 0 touches global.
    float carry = 0.0f;
    if (seg > 0) {
        if (s == 0) {
            const int pidx = (seg - 1) * NGRP + grp;
            const volatile unsigned* f = &g_flag[pidx];
            while (*f == 0u) { __nanosleep(40); }
            __threadfence();
            carrySh[lane] = *((const volatile float*)&g_carry[pidx * 32 + lane]);
        }
        __syncthreads();
        carry = carrySh[lane];
    }

    #pragma unroll
    for (int k = 0; k < NCHSEG; k++) {
        const int p = k & 1;

        // Prefetch next chunk of this segment.
        const float* xpn = xp + (size_t)CHUNK * CH;
        if (k + 1 < NCHSEG) {
            #pragma unroll
            for (int i = 0; i < TSUB; i++) xb[i] = xpn[(size_t)i * CH];
        }

        // Local serial scan in place (zero initial condition).
        #pragma unroll
        for (int i = 1; i < TSUB; i++) xa[i] = fmaf(dc, xa[i - 1], xa[i]);

        subAgg[p][s][lane] = xa[TSUB - 1];
        __syncthreads();

        // Every warp redundantly combines the 8 subtile aggregates.
        float P;                             // state entering subtile s
        {
            float r = carry;
            P = r;                           // valid if s == 0
            #pragma unroll
            for (int j = 0; j < NSUB; j++) {
                const float aggj = subAgg[p][j][lane];
                r = fmaf(dT, r, aggj);       // state entering subtile j+1
                if (j + 1 == s) P = r;
            }
            carry = r;                       // state entering next chunk
        }

        // Publish segment-inclusive carry ASAP (before the store loop) so
        // the successor's spin ends while this block still has stores to do.
        if (k == NCHSEG - 1 && seg != SEGS - 1 && s == 0) {
            const int midx = seg * NGRP + grp;
            *((volatile float*)&g_carry[midx * 32 + lane]) = carry;
            __threadfence();
            if (lane == 0) *((volatile unsigned*)&g_flag[midx]) = 1u;
        }

        // Correction + store: y_i = ylocal_i + dc^(i+1) * P
        float f = dc;
        #pragma unroll
        for (int i = 0; i < TSUB; i++) {
            yp[(size_t)i * CH] = fmaf(f, P, xa[i]);
            f *= dc;
        }

        // Rotate buffers.
        #pragma unroll
        for (int i = 0; i < TSUB; i++) xa[i] = xb[i];

        xp += (size_t)CHUNK * CH;
        yp += (size_t)CHUNK * CH;
    }
}

extern "C" void kernel_launch(void* const* d_in, const int* in_sizes, int n_in,
                              void* d_out, int out_size)
{
    const float* x = (const float*)d_in[0];
    const float* d = (const float*)d_in[1];
    float*       y = (float*)d_out;
    (void)in_sizes; (void)n_in; (void)out_size;

    init_flags_kernel<<<(SEGS * NGRP + 255) / 256, 256>>>();
    cummulsum_kernel<<<SEGS * NGRP, NTHR>>>(x, d, y);
}

// round 9
// speedup vs baseline: 1.2986x; 1.2986x over previous
#include <cuda_runtime.h>
#include <cuda_bf16.h>
#include <cstdint>

// y_t = d*y_{t-1} + x_t   per channel, y_{-1} = 0  (so y_0 = x_0)
// x: [BSZ=8, SEQ=4096, CH=1024] fp32, d: [CH] fp32, out same shape as x.
//
// One block per (batch, 32-channel group) column = 256 blocks,
// 256 threads = NSUB(8) t-subtiles x 32 channels, 2 blocks/SM (80 regs).
// 32 chunks of 128 timesteps; per chunk: register-local serial scan,
// one bar.sync (subAgg parity-double-buffered), then EVERY warp redundantly
// combines the 8 subtile aggregates (multiplier d^16) keeping a replicated
// carry register -> no warp-0 critical section.
//
// R9: best-known structure (R5) + streaming cache hints: x is read once
// (__ldcs, evict-first) and y is written once, never re-read (__stcs),
// keeping L2 available for the read stream. Single kernel launch.

#define BSZ    8
#define SEQ    4096
#define CH     1024
#define TSUB   16
#define NSUB   8
#define NTHR   (NSUB * 32)          // 256
#define CHUNK  (TSUB * NSUB)        // 128
#define NCHUNK (SEQ / CHUNK)        // 32
#define CGRPS  (CH / 32)            // 32 channel groups per batch

__global__ __launch_bounds__(NTHR, 2)
void cummulsum_kernel(const float* __restrict__ x,
                      const float* __restrict__ d,
                      float* __restrict__ y)
{
    __shared__ float subAgg[2][NSUB][32];   // double-buffered by chunk parity

    const int tid  = threadIdx.x;
    const int lane = tid & 31;
    const int s    = tid >> 5;          // subtile index 0..7
    const int b    = blockIdx.x >> 5;   // batch 0..7
    const int cg   = blockIdx.x & 31;   // channel group 0..31
    const int c    = cg * 32 + lane;    // channel

    const float dc = __ldg(d + c);
    // dT = dc^TSUB = dc^16
    float dT = dc * dc;  dT = dT * dT;  dT = dT * dT;  dT = dT * dT;

    const size_t colBase = ((size_t)b * SEQ) * CH + (size_t)c;
    const float* xp = x + colBase + (size_t)(s * TSUB) * CH;
    float*       yp = y + colBase + (size_t)(s * TSUB) * CH;

    float carry = 0.0f;   // replicated per-warp running state (identical in all warps)

    float xa[TSUB];
    float xb[TSUB];

    // Prologue: load chunk 0 (streaming: single-use data)
    #pragma unroll
    for (int i = 0; i < TSUB; i++) xa[i] = __ldcs(xp + (size_t)i * CH);

    #pragma unroll 2
    for (int k = 0; k < NCHUNK; k++) {
        const int p = k & 1;

        // Prefetch next chunk; independent of everything below.
        const float* xpn = xp + (size_t)CHUNK * CH;
        if (k + 1 < NCHUNK) {
            #pragma unroll
            for (int i = 0; i < TSUB; i++) xb[i] = __ldcs(xpn + (size_t)i * CH);
        }

        // Local serial scan in place (zero initial condition)
        #pragma unroll
        for (int i = 1; i < TSUB; i++) xa[i] = fmaf(dc, xa[i - 1], xa[i]);

        subAgg[p][s][lane] = xa[TSUB - 1];
        __syncthreads();

        // Every warp redundantly combines the 8 subtile aggregates; uses the
        // prefix for its own subtile and updates its replicated carry.
        float P;                         // state entering subtile s
        {
            float r = carry;
            P = r;                       // valid if s == 0
            #pragma unroll
            for (int j = 0; j < NSUB; j++) {
                const float aggj = subAgg[p][j][lane];
                r = fmaf(dT, r, aggj);   // state entering subtile j+1
                if (j + 1 == s) P = r;
            }
            carry = r;                   // state entering next chunk
        }

        // Correction + store: y_i = ylocal_i + dc^(i+1) * P
        // (serial f chain is throughput-only; hidden by warp interleaving)
        float f = dc;
        #pragma unroll
        for (int i = 0; i < TSUB; i++) {
            __stcs(yp + (size_t)i * CH, fmaf(f, P, xa[i]));
            f *= dc;
        }

        // Rotate buffers (dead on the final iteration; guarded)
        if (k + 1 < NCHUNK) {
            #pragma unroll
            for (int i = 0; i < TSUB; i++) xa[i] = xb[i];
        }

        xp += (size_t)CHUNK * CH;
        yp += (size_t)CHUNK * CH;
    }
}

extern "C" void kernel_launch(void* const* d_in, const int* in_sizes, int n_in,
                              void* d_out, int out_size)
{
    const float* x = (const float*)d_in[0];
    const float* d = (const float*)d_in[1];
    float*       y = (float*)d_out;
    (void)in_sizes; (void)n_in; (void)out_size;

    cummulsum_kernel<<<BSZ * CGRPS, NTHR>>>(x, d, y);
}